// round 12
// baseline (speedup 1.0000x reference)
#include <cuda_runtime.h>
#include <cuda_bf16.h>
#include <cstdint>

// Problem constants
#define B_    2
#define N_    2048
#define DIM_  1024
#define H_    16
#define HD_   64
#define M_    (B_ * N_)          // 4096
#define SCALE_ 0.125f

// Scratch (__device__ globals — allocation guards forbid cudaMalloc)
__device__ float g_qkv[(size_t)M_ * 3 * DIM_];           // [4096, 3072]
__device__ float g_attn[(size_t)M_ * DIM_];              // [4096, 1024]

// ---------------------------------------------------------------------------
// tf32 helpers
// ---------------------------------------------------------------------------
__device__ __forceinline__ uint32_t f2tf32(float x) {
    uint32_t r;
    asm("cvt.rna.tf32.f32 %0, %1;" : "=r"(r) : "f"(x));
    return r;
}

__device__ __forceinline__ void mma_tf32(float c[4], const uint32_t a[4],
                                         const uint32_t b0, const uint32_t b1) {
    asm volatile(
        "mma.sync.aligned.m16n8k8.row.col.f32.tf32.tf32.f32 "
        "{%0,%1,%2,%3}, {%4,%5,%6,%7}, {%8,%9}, {%0,%1,%2,%3};"
        : "+f"(c[0]), "+f"(c[1]), "+f"(c[2]), "+f"(c[3])
        : "r"(a[0]), "r"(a[1]), "r"(a[2]), "r"(a[3]), "r"(b0), "r"(b1));
}

// Fragment-layout conventions for m16n8k8 tf32 (lane = g*4+tg, g=lane>>2):
//  A operand (16 rows x 8 k): value (ri,ki) -> lane=(ri&7)*4+(ki&3),
//      reg = ((ri>>3)&1) + 2*((ki&7)>>2).   Layout [mblk][kb][33][4].
//  B operand (8 n x 8 k):     value (ni,ki) -> lane=(ni&7)*4+(ki&3),
//      reg = (ki&7)>>2.                      Layout [nblk][kb][33][2].
// Frag read = one LDS.128 (A) / LDS.64 (B), conflict-free.

// ---------------------------------------------------------------------------
// tf32 GEMM: C = A @ B^T (+ bias). BM=BN=128, BK=32, 256 thr, 2 CTAs/SM.
// Single smem buffer, fragment-ordered layout.
// ---------------------------------------------------------------------------
__global__ void __launch_bounds__(256, 2)
gemm_tf32(const float* __restrict__ A, const float* __restrict__ Bm,
          const float* __restrict__ bias, float* __restrict__ C,
          int Kd, int lda, int ldb, int ldc)
{
    __shared__ uint32_t As[8][4][33][4];    // 16.9 KB
    __shared__ uint32_t Bs[16][4][33][2];   // 16.9 KB

    const int tid  = threadIdx.x;
    const int warp = tid >> 5, lane = tid & 31;
    const int g    = lane >> 2, tg = lane & 3;
    const int wm   = (warp & 1) * 64;
    const int wn   = (warp >> 1) * 32;
    const int mb0  = (warp & 1) * 4;
    const int nb0  = (warp >> 1) * 4;
    const int rowBase = blockIdx.y * 128;
    const int colBase = blockIdx.x * 128;

    const int lr   = tid >> 3;           // 0..31
    const int lkq  = (tid & 7) * 4;      // 0..28
    const int lkb  = lkq >> 3;
    const int regB = (lkq & 7) >> 2;     // 0 or 1
    const int regA2 = 2 * regB;

    float acc[4][4][4];
#pragma unroll
    for (int i = 0; i < 4; i++)
#pragma unroll
        for (int j = 0; j < 4; j++)
#pragma unroll
            for (int e = 0; e < 4; e++) acc[i][j][e] = 0.f;

    for (int k0 = 0; k0 < Kd; k0 += 32) {
#pragma unroll
        for (int i = 0; i < 4; i++) {
            int r = i * 32 + lr;
            float4 va = *(const float4*)(A  + (size_t)(rowBase + r) * lda + k0 + lkq);
            float4 vb = *(const float4*)(Bm + (size_t)(colBase + r) * ldb + k0 + lkq);
            int regA = ((r >> 3) & 1) + regA2;
            uint32_t* ap = &As[r >> 4][lkb][(r & 7) * 4][regA];  // lane stride 4
            ap[0]  = f2tf32(va.x);
            ap[4]  = f2tf32(va.y);
            ap[8]  = f2tf32(va.z);
            ap[12] = f2tf32(va.w);
            uint32_t* bp = &Bs[r >> 3][lkb][(r & 7) * 4][regB];  // lane stride 2
            bp[0] = f2tf32(vb.x);
            bp[2] = f2tf32(vb.y);
            bp[4] = f2tf32(vb.z);
            bp[6] = f2tf32(vb.w);
        }
        __syncthreads();

#pragma unroll
        for (int kb = 0; kb < 4; kb++) {
            uint32_t af[4][4];
#pragma unroll
            for (int mt = 0; mt < 4; mt++)
                *(uint4*)&af[mt][0] = *(const uint4*)&As[mb0 + mt][kb][lane][0];
#pragma unroll
            for (int nt = 0; nt < 4; nt++) {
                uint2 bf = *(const uint2*)&Bs[nb0 + nt][kb][lane][0];
#pragma unroll
                for (int mt = 0; mt < 4; mt++)
                    mma_tf32(acc[mt][nt], af[mt], bf.x, bf.y);
            }
        }
        __syncthreads();
    }

    // ---- epilogue ----
#pragma unroll
    for (int mt = 0; mt < 4; mt++) {
#pragma unroll
        for (int nt = 0; nt < 4; nt++) {
            int r = rowBase + wm + mt * 16 + g;
            int c = colBase + wn + nt * 8 + 2 * tg;
            float2 v0 = make_float2(acc[mt][nt][0], acc[mt][nt][1]);
            float2 v1 = make_float2(acc[mt][nt][2], acc[mt][nt][3]);
            if (bias) {
                float2 bb = *(const float2*)(bias + c);
                v0.x += bb.x; v0.y += bb.y;
                v1.x += bb.x; v1.y += bb.y;
            }
            *(float2*)(C + (size_t)r * ldc + c)       = v0;
            *(float2*)(C + (size_t)(r + 8) * ldc + c) = v1;
        }
    }
}

// ---------------------------------------------------------------------------
// Fused flash attention, tf32, pipelined; K/V in fragment-ordered smem.
// Grid (N/128, H, B), 256 thr = 8 warps; warp w owns q rows [w*16, w*16+16).
// Smem words: Ks[16][8][33][2]=8448, Vs[8][16][33][2]=8448, Ps[128][132]=16896.
// ---------------------------------------------------------------------------
#define KS_WORDS (16 * 8 * 33 * 2)
#define VS_WORDS (8 * 16 * 33 * 2)
#define PS_STRIDE 132
#define FLASH_SMEM ((KS_WORDS + VS_WORDS + 128 * PS_STRIDE) * 4)

__global__ void __launch_bounds__(256, 1)
flash_attn(const float* __restrict__ qkv, float* __restrict__ attn_out)
{
    extern __shared__ uint32_t sm[];
    typedef uint32_t KsT[8][33][2];
    typedef uint32_t VsT[16][33][2];
    KsT* Ks = (KsT*)sm;                              // Ks[16]
    VsT* Vs = (VsT*)(sm + KS_WORDS);                 // Vs[8]
    uint32_t (*Ps)[PS_STRIDE] =
        (uint32_t(*)[PS_STRIDE])(sm + KS_WORDS + VS_WORDS);

    const int tid  = threadIdx.x;
    const int warp = tid >> 5, lane = tid & 31;
    const int g    = lane >> 2, tg = lane & 3;
    const int wm   = warp * 16;
    const int mt   = blockIdx.x;
    const int h    = blockIdx.y;
    const int b    = blockIdx.z;

    const float* base = qkv + (size_t)b * N_ * 3 * DIM_;

    // loader coordinates: i in [0,8), row r = i*16 + lr, cols ldq..ldq+3
    const int lr  = tid >> 4;
    const int ldq = (tid & 15) * 4;
    // K store (B-frag over k-dim=d): fixed parts
    const int kKb   = ldq >> 3;
    const int kReg  = (ldq & 7) >> 2;
    // V store (B-frag over n-dim=d, k-dim=key): fixed parts
    const int vNb   = ldq >> 3;
    const int vLane0 = (ldq & 7) * 4;     // + c*4 + (r&3)

    // ---- Prologue: Q tile -> Ps staging -> frags ----
#pragma unroll
    for (int i = 0; i < 8; i++) {
        int r = i * 16 + lr;
        float4 v = *(const float4*)(base + (size_t)(mt * 128 + r) * 3 * DIM_
                                    + h * HD_ + ldq);
        Ps[r][ldq + 0] = f2tf32(v.x * SCALE_);
        Ps[r][ldq + 1] = f2tf32(v.y * SCALE_);
        Ps[r][ldq + 2] = f2tf32(v.z * SCALE_);
        Ps[r][ldq + 3] = f2tf32(v.w * SCALE_);
    }
    __syncthreads();

    uint32_t qf[8][4];
#pragma unroll
    for (int kk = 0; kk < 8; kk++) {
        qf[kk][0] = Ps[wm + g][kk * 8 + tg];
        qf[kk][1] = Ps[wm + 8 + g][kk * 8 + tg];
        qf[kk][2] = Ps[wm + g][kk * 8 + tg + 4];
        qf[kk][3] = Ps[wm + 8 + g][kk * 8 + tg + 4];
    }
    __syncthreads();

    // ---- Prologue: K/V tile 0 -> fragment-ordered smem ----
#pragma unroll
    for (int i = 0; i < 8; i++) {
        int r = i * 16 + lr;
        const float* kp = base + (size_t)r * 3 * DIM_ + DIM_ + h * HD_ + ldq;
        float4 v = *(const float4*)kp;
        uint32_t* ks = &Ks[r >> 3][kKb][(r & 7) * 4][kReg];
        ks[0] = f2tf32(v.x); ks[2] = f2tf32(v.y);
        ks[4] = f2tf32(v.z); ks[6] = f2tf32(v.w);
        float4 w = *(const float4*)(kp + DIM_);
        uint32_t* vs = &Vs[vNb][r >> 3][vLane0 + (r & 3)][(r >> 2) & 1];
        vs[0]  = f2tf32(w.x); vs[8]  = f2tf32(w.y);
        vs[16] = f2tf32(w.z); vs[24] = f2tf32(w.w);
    }
    __syncthreads();

    float o[8][4];
#pragma unroll
    for (int nt = 0; nt < 8; nt++)
#pragma unroll
        for (int e = 0; e < 4; e++) o[nt][e] = 0.f;
    float m0 = -1e30f, m1 = -1e30f, l0 = 0.f, l1 = 0.f;

    constexpr int NT = N_ / 128;
    for (int kt = 0; kt < NT; kt++) {
        const bool more = (kt + 1 < NT);

        // ---- S = Q @ K^T : warp strip [16 x 128] ----
        float sacc[16][4];
#pragma unroll
        for (int nt = 0; nt < 16; nt++)
#pragma unroll
            for (int e = 0; e < 4; e++) sacc[nt][e] = 0.f;
#pragma unroll
        for (int kb = 0; kb < 8; kb++) {
#pragma unroll
            for (int nt = 0; nt < 16; nt++) {
                uint2 bf = *(const uint2*)&Ks[nt][kb][lane][0];
                mma_tf32(sacc[nt], qf[kb], bf.x, bf.y);
            }
        }

        // issue next-K loads (hidden under softmax)
        float4 pk[8];
        if (more) {
#pragma unroll
            for (int i = 0; i < 8; i++) {
                int r = i * 16 + lr;
                pk[i] = *(const float4*)(base
                        + (size_t)((kt + 1) * 128 + r) * 3 * DIM_
                        + DIM_ + h * HD_ + ldq);
            }
        }

        // ---- online softmax (rows wm+g, wm+8+g) ----
        float mx0 = -1e30f, mx1 = -1e30f;
#pragma unroll
        for (int nt = 0; nt < 16; nt++) {
            mx0 = fmaxf(mx0, fmaxf(sacc[nt][0], sacc[nt][1]));
            mx1 = fmaxf(mx1, fmaxf(sacc[nt][2], sacc[nt][3]));
        }
        mx0 = fmaxf(mx0, __shfl_xor_sync(~0u, mx0, 1));
        mx0 = fmaxf(mx0, __shfl_xor_sync(~0u, mx0, 2));
        mx1 = fmaxf(mx1, __shfl_xor_sync(~0u, mx1, 1));
        mx1 = fmaxf(mx1, __shfl_xor_sync(~0u, mx1, 2));

        float mn0 = fmaxf(m0, mx0), mn1 = fmaxf(m1, mx1);
        float c0 = __expf(m0 - mn0), c1 = __expf(m1 - mn1);
        l0 *= c0; l1 *= c1;
#pragma unroll
        for (int nt = 0; nt < 8; nt++) {
            o[nt][0] *= c0; o[nt][1] *= c0;
            o[nt][2] *= c1; o[nt][3] *= c1;
        }

        float s0 = 0.f, s1 = 0.f;
#pragma unroll
        for (int nt = 0; nt < 16; nt++) {
            float p0 = __expf(sacc[nt][0] - mn0);
            float p1 = __expf(sacc[nt][1] - mn0);
            float p2 = __expf(sacc[nt][2] - mn1);
            float p3 = __expf(sacc[nt][3] - mn1);
            s0 += p0 + p1; s1 += p2 + p3;
            int c = nt * 8 + 2 * tg;
            *(uint2*)&Ps[wm + g][c]     = make_uint2(f2tf32(p0), f2tf32(p1));
            *(uint2*)&Ps[wm + 8 + g][c] = make_uint2(f2tf32(p2), f2tf32(p3));
        }
        s0 += __shfl_xor_sync(~0u, s0, 1);
        s0 += __shfl_xor_sync(~0u, s0, 2);
        s1 += __shfl_xor_sync(~0u, s1, 1);
        s1 += __shfl_xor_sync(~0u, s1, 2);
        l0 += s0; l1 += s1;
        m0 = mn0; m1 = mn1;
        __syncthreads();   // (A) all S-mma done, Ps ready

        // issue next-V loads (hidden under PV-mma)
        float4 pv[8];
        if (more) {
#pragma unroll
            for (int i = 0; i < 8; i++) {
                int r = i * 16 + lr;
                pv[i] = *(const float4*)(base
                        + (size_t)((kt + 1) * 128 + r) * 3 * DIM_
                        + 2 * DIM_ + h * HD_ + ldq);
            }
        }

        // ---- O += P @ V ----
#pragma unroll
        for (int kk = 0; kk < 16; kk++) {
            uint32_t af[4];
            af[0] = Ps[wm + g][kk * 8 + tg];
            af[1] = Ps[wm + 8 + g][kk * 8 + tg];
            af[2] = Ps[wm + g][kk * 8 + tg + 4];
            af[3] = Ps[wm + 8 + g][kk * 8 + tg + 4];
#pragma unroll
            for (int nt = 0; nt < 8; nt++) {
                uint2 bf = *(const uint2*)&Vs[nt][kk][lane][0];
                mma_tf32(o[nt], af, bf.x, bf.y);
            }
        }

        if (more) {
            // store next K (safe: sync A guarantees all S-mma finished)
#pragma unroll
            for (int i = 0; i < 8; i++) {
                int r = i * 16 + lr;
                uint32_t* ks = &Ks[r >> 3][kKb][(r & 7) * 4][kReg];
                ks[0] = f2tf32(pk[i].x); ks[2] = f2tf32(pk[i].y);
                ks[4] = f2tf32(pk[i].z); ks[6] = f2tf32(pk[i].w);
            }
        }
        __syncthreads();   // (B) all PV-mma done -> Vs writable
        if (more) {
#pragma unroll
            for (int i = 0; i < 8; i++) {
                int r = i * 16 + lr;
                uint32_t* vs = &Vs[vNb][r >> 3][vLane0 + (r & 3)][(r >> 2) & 1];
                vs[0]  = f2tf32(pv[i].x); vs[8]  = f2tf32(pv[i].y);
                vs[16] = f2tf32(pv[i].z); vs[24] = f2tf32(pv[i].w);
            }
        }
    }

    // ---- Epilogue ----
    const float inv0 = 1.f / l0, inv1 = 1.f / l1;
    float* out0 = attn_out + (size_t)(b * N_ + mt * 128 + wm + g) * DIM_ + h * HD_;
    float* out1 = out0 + (size_t)8 * DIM_;
#pragma unroll
    for (int nt = 0; nt < 8; nt++) {
        int c = nt * 8 + 2 * tg;
        *(float2*)(out0 + c) = make_float2(o[nt][0] * inv0, o[nt][1] * inv0);
        *(float2*)(out1 + c) = make_float2(o[nt][2] * inv1, o[nt][3] * inv1);
    }
}

// ---------------------------------------------------------------------------
extern "C" void kernel_launch(void* const* d_in, const int* in_sizes, int n_in,
                              void* d_out, int out_size)
{
    const float* x      = (const float*)d_in[0];   // [2,2048,1024]
    const float* w_qkv  = (const float*)d_in[1];   // [3072,1024]
    const float* w_proj = (const float*)d_in[2];   // [1024,1024]
    const float* b_proj = (const float*)d_in[3];   // [1024]
    float* out = (float*)d_out;                    // [2,2048,1024]

    float *qkv, *attn;
    cudaGetSymbolAddress((void**)&qkv,  g_qkv);
    cudaGetSymbolAddress((void**)&attn, g_attn);

    // Idempotent host-side config; executed identically on every call
    // (capture-safe, no stream operations).
    cudaFuncSetAttribute(flash_attn,
                         cudaFuncAttributeMaxDynamicSharedMemorySize,
                         FLASH_SMEM);

    // 1) qkv = x @ w_qkv^T   [4096,3072]
    gemm_tf32<<<dim3(3 * DIM_ / 128, M_ / 128), 256>>>(
        x, w_qkv, nullptr, qkv, DIM_, DIM_, DIM_, 3 * DIM_);

    // 2) fused attention -> [B,N,H,Dh] = [4096,1024]
    flash_attn<<<dim3(N_ / 128, H_, B_), 256, FLASH_SMEM>>>(qkv, attn);

    // 3) out = attn @ w_proj^T + b_proj
    gemm_tf32<<<dim3(DIM_ / 128, M_ / 128), 256>>>(
        attn, w_proj, b_proj, out, DIM_, DIM_, DIM_, DIM_);
}

// round 13
// speedup vs baseline: 1.6188x; 1.6188x over previous
#include <cuda_runtime.h>
#include <cuda_bf16.h>
#include <cstdint>

// Problem constants
#define B_    2
#define N_    2048
#define DIM_  1024
#define H_    16
#define HD_   64
#define M_    (B_ * N_)          // 4096
#define SCALE_ 0.125f

// Scratch (__device__ globals — allocation guards forbid cudaMalloc)
__device__ float g_qkv[(size_t)M_ * 3 * DIM_];           // [4096, 3072]
__device__ float g_attn[(size_t)M_ * DIM_];              // [4096, 1024]
__device__ float g_x[(size_t)M_ * DIM_];                 // rounded x
__device__ float g_wqkv[(size_t)3 * DIM_ * DIM_];        // rounded w_qkv
__device__ float g_wproj[(size_t)DIM_ * DIM_];           // rounded w_proj

// ---------------------------------------------------------------------------
// tf32 helpers
// ---------------------------------------------------------------------------
__device__ __forceinline__ uint32_t f2tf32(float x) {
    uint32_t r;
    asm("cvt.rna.tf32.f32 %0, %1;" : "=r"(r) : "f"(x));
    return r;
}
__device__ __forceinline__ float f2tf32f(float x) {
    return __uint_as_float(f2tf32(x));
}

__device__ __forceinline__ void mma_tf32(float c[4], const uint32_t a[4],
                                         const uint32_t b0, const uint32_t b1) {
    asm volatile(
        "mma.sync.aligned.m16n8k8.row.col.f32.tf32.tf32.f32 "
        "{%0,%1,%2,%3}, {%4,%5,%6,%7}, {%8,%9}, {%0,%1,%2,%3};"
        : "+f"(c[0]), "+f"(c[1]), "+f"(c[2]), "+f"(c[3])
        : "r"(a[0]), "r"(a[1]), "r"(a[2]), "r"(a[3]), "r"(b0), "r"(b1));
}

__device__ __forceinline__ void cpasync16(uint32_t s, const void* g) {
    asm volatile("cp.async.cg.shared.global [%0], [%1], 16;" :: "r"(s), "l"(g));
}

// ---------------------------------------------------------------------------
// Elementwise tf32 rounding (inputs pre-pass). n multiple of 1024.
// ---------------------------------------------------------------------------
__global__ void __launch_bounds__(256)
round_tf32(const float* __restrict__ in, float* __restrict__ out, int n4)
{
    int i = blockIdx.x * 256 + threadIdx.x;
    if (i < n4) {
        float4 v = ((const float4*)in)[i];
        v.x = f2tf32f(v.x); v.y = f2tf32f(v.y);
        v.z = f2tf32f(v.z); v.w = f2tf32f(v.w);
        ((float4*)out)[i] = v;
    }
}

// ---------------------------------------------------------------------------
// cp.async 2-stage tf32 GEMM: C = A @ B^T (+ bias).
// Inputs MUST be pre-rounded to tf32 values (raw bits fed to mma).
// BM=BN=128, BK=32, 256 thr, 2 CTAs/SM. Dynamic smem 73728 B.
// roundOut: round outputs to tf32 (for tensors consumed by later tf32 mma).
// ---------------------------------------------------------------------------
#define GSTRIDE 36
#define GSTAGE  (128 * GSTRIDE)               // words per matrix per stage
#define GEMM_SMEM (4 * GSTAGE * 4)            // 2 stages x (A+B) = 73728 B

__global__ void __launch_bounds__(256, 2)
gemm_cp(const float* __restrict__ A, const float* __restrict__ Bm,
        const float* __restrict__ bias, float* __restrict__ C,
        int Kd, int lda, int ldb, int ldc, int roundOut)
{
    extern __shared__ uint32_t gs[];
    // layout: As[2][128][36] then Bs[2][128][36]
    uint32_t (*As)[128][GSTRIDE] = (uint32_t(*)[128][GSTRIDE])gs;
    uint32_t (*Bs)[128][GSTRIDE] = (uint32_t(*)[128][GSTRIDE])(gs + 2 * GSTAGE);
    const uint32_t smemBase = (uint32_t)__cvta_generic_to_shared(gs);

    const int tid  = threadIdx.x;
    const int warp = tid >> 5, lane = tid & 31;
    const int g    = lane >> 2, tg = lane & 3;
    const int wm   = (warp & 1) * 64;
    const int wn   = (warp >> 1) * 32;
    const int rowBase = blockIdx.y * 128;
    const int colBase = blockIdx.x * 128;

    const int lr  = tid >> 3;            // 0..31
    const int lkq = (tid & 7) * 4;       // 0,4,...,28

    float acc[4][4][4];
#pragma unroll
    for (int i = 0; i < 4; i++)
#pragma unroll
        for (int j = 0; j < 4; j++)
#pragma unroll
            for (int e = 0; e < 4; e++) acc[i][j][e] = 0.f;

    const int nTiles = Kd / 32;

    // stage loader: 4 x 16B for A, 4 x 16B for B
    auto load_stage = [&](int t, int s) {
        int k0 = t * 32;
#pragma unroll
        for (int i = 0; i < 4; i++) {
            int r = i * 32 + lr;
            cpasync16(smemBase + (uint32_t)(((s * 128 + r) * GSTRIDE + lkq) * 4),
                      A + (size_t)(rowBase + r) * lda + k0 + lkq);
            cpasync16(smemBase + (uint32_t)(((2 * GSTAGE) + (s * 128 + r) * GSTRIDE + lkq) * 4),
                      Bm + (size_t)(colBase + r) * ldb + k0 + lkq);
        }
        asm volatile("cp.async.commit_group;");
    };

    load_stage(0, 0);

    int buf = 0;
    for (int t = 0; t < nTiles; t++) {
        if (t + 1 < nTiles) {
            load_stage(t + 1, buf ^ 1);
            asm volatile("cp.async.wait_group 1;");
        } else {
            asm volatile("cp.async.wait_group 0;");
        }
        __syncthreads();   // stage t resident in buf, visible to all

#pragma unroll
        for (int kb = 0; kb < 4; kb++) {
            const int kk = kb * 8;
            uint32_t af[4][4];
#pragma unroll
            for (int mt = 0; mt < 4; mt++) {
                int r0 = wm + mt * 16 + g;
                af[mt][0] = As[buf][r0][kk + tg];
                af[mt][1] = As[buf][r0 + 8][kk + tg];
                af[mt][2] = As[buf][r0][kk + tg + 4];
                af[mt][3] = As[buf][r0 + 8][kk + tg + 4];
            }
#pragma unroll
            for (int nt = 0; nt < 4; nt++) {
                int n0 = wn + nt * 8 + g;
                uint32_t b0 = Bs[buf][n0][kk + tg];
                uint32_t b1 = Bs[buf][n0][kk + tg + 4];
#pragma unroll
                for (int mt = 0; mt < 4; mt++)
                    mma_tf32(acc[mt][nt], af[mt], b0, b1);
            }
        }
        __syncthreads();   // all reads of buf done before it is reloaded
        buf ^= 1;
    }

    // ---- epilogue ----
#pragma unroll
    for (int mt = 0; mt < 4; mt++) {
#pragma unroll
        for (int nt = 0; nt < 4; nt++) {
            int r = rowBase + wm + mt * 16 + g;
            int c = colBase + wn + nt * 8 + 2 * tg;
            float2 v0 = make_float2(acc[mt][nt][0], acc[mt][nt][1]);
            float2 v1 = make_float2(acc[mt][nt][2], acc[mt][nt][3]);
            if (bias) {
                float2 bb = *(const float2*)(bias + c);
                v0.x += bb.x; v0.y += bb.y;
                v1.x += bb.x; v1.y += bb.y;
            }
            if (roundOut) {
                v0.x = f2tf32f(v0.x); v0.y = f2tf32f(v0.y);
                v1.x = f2tf32f(v1.x); v1.y = f2tf32f(v1.y);
            }
            *(float2*)(C + (size_t)r * ldc + c)       = v0;
            *(float2*)(C + (size_t)(r + 8) * ldc + c) = v1;
        }
    }
}

// ---------------------------------------------------------------------------
// Fused flash attention, tf32, pipelined (R8 structure — known good).
// Grid (N/128, H, B), 256 thr = 8 warps; warp w owns q rows [w*16, w*16+16).
// qkv is pre-rounded to tf32 values, so internal cvts are idempotent.
// Epilogue rounds outputs (consumed by the proj tf32 GEMM).
// ---------------------------------------------------------------------------
#define KSTRIDE 68
#define VSTRIDE 132
#define PSTRIDE 132
#define FLASH_SMEM ((128 * KSTRIDE + 64 * VSTRIDE + 128 * PSTRIDE) * 4)

__global__ void __launch_bounds__(256, 1)
flash_attn(const float* __restrict__ qkv, float* __restrict__ attn_out)
{
    extern __shared__ uint32_t sm[];
    uint32_t (*Ks)[KSTRIDE] = (uint32_t(*)[KSTRIDE])sm;
    uint32_t (*Vs)[VSTRIDE] = (uint32_t(*)[VSTRIDE])(sm + 128 * KSTRIDE);
    uint32_t (*Ps)[PSTRIDE] =
        (uint32_t(*)[PSTRIDE])(sm + 128 * KSTRIDE + 64 * VSTRIDE);

    const int tid  = threadIdx.x;
    const int warp = tid >> 5, lane = tid & 31;
    const int g    = lane >> 2, tg = lane & 3;
    const int wm   = warp * 16;
    const int mt   = blockIdx.x;
    const int h    = blockIdx.y;
    const int b    = blockIdx.z;

    const float* base = qkv + (size_t)b * N_ * 3 * DIM_;

    const int lr  = tid >> 4;
    const int ldq = (tid & 15) * 4;

    // ---- Prologue: Q tile -> Ps staging -> frags ----
#pragma unroll
    for (int i = 0; i < 8; i++) {
        int r = i * 16 + lr;
        float4 v = *(const float4*)(base + (size_t)(mt * 128 + r) * 3 * DIM_
                                    + h * HD_ + ldq);
        Ps[r][ldq + 0] = f2tf32(v.x * SCALE_);
        Ps[r][ldq + 1] = f2tf32(v.y * SCALE_);
        Ps[r][ldq + 2] = f2tf32(v.z * SCALE_);
        Ps[r][ldq + 3] = f2tf32(v.w * SCALE_);
    }
    __syncthreads();

    uint32_t qf[8][4];
#pragma unroll
    for (int kk = 0; kk < 8; kk++) {
        qf[kk][0] = Ps[wm + g][kk * 8 + tg];
        qf[kk][1] = Ps[wm + 8 + g][kk * 8 + tg];
        qf[kk][2] = Ps[wm + g][kk * 8 + tg + 4];
        qf[kk][3] = Ps[wm + 8 + g][kk * 8 + tg + 4];
    }
    __syncthreads();

    // ---- Prologue: K/V tile 0 -> smem ----
#pragma unroll
    for (int i = 0; i < 8; i++) {
        int r = i * 16 + lr;
        const float* kp = base + (size_t)r * 3 * DIM_ + DIM_ + h * HD_ + ldq;
        float4 v = *(const float4*)kp;
        *(uint4*)&Ks[r][ldq] =
            make_uint4(f2tf32(v.x), f2tf32(v.y), f2tf32(v.z), f2tf32(v.w));
        float4 w = *(const float4*)(kp + DIM_);
        Vs[ldq + 0][r] = f2tf32(w.x);
        Vs[ldq + 1][r] = f2tf32(w.y);
        Vs[ldq + 2][r] = f2tf32(w.z);
        Vs[ldq + 3][r] = f2tf32(w.w);
    }
    __syncthreads();

    float o[8][4];
#pragma unroll
    for (int nt = 0; nt < 8; nt++)
#pragma unroll
        for (int e = 0; e < 4; e++) o[nt][e] = 0.f;
    float m0 = -1e30f, m1 = -1e30f, l0 = 0.f, l1 = 0.f;

    constexpr int NT = N_ / 128;
    for (int kt = 0; kt < NT; kt++) {
        const bool more = (kt + 1 < NT);

        // ---- S = Q @ K^T ----
        float sacc[16][4];
#pragma unroll
        for (int nt = 0; nt < 16; nt++)
#pragma unroll
            for (int e = 0; e < 4; e++) sacc[nt][e] = 0.f;
#pragma unroll
        for (int kk = 0; kk < 8; kk++) {
#pragma unroll
            for (int nt = 0; nt < 16; nt++) {
                uint32_t b0 = Ks[nt * 8 + g][kk * 8 + tg];
                uint32_t b1 = Ks[nt * 8 + g][kk * 8 + tg + 4];
                mma_tf32(sacc[nt], qf[kk], b0, b1);
            }
        }

        // issue next-K loads (hidden under softmax)
        float4 pk[8];
        if (more) {
#pragma unroll
            for (int i = 0; i < 8; i++) {
                int r = i * 16 + lr;
                pk[i] = *(const float4*)(base
                        + (size_t)((kt + 1) * 128 + r) * 3 * DIM_
                        + DIM_ + h * HD_ + ldq);
            }
        }

        // ---- online softmax ----
        float mx0 = -1e30f, mx1 = -1e30f;
#pragma unroll
        for (int nt = 0; nt < 16; nt++) {
            mx0 = fmaxf(mx0, fmaxf(sacc[nt][0], sacc[nt][1]));
            mx1 = fmaxf(mx1, fmaxf(sacc[nt][2], sacc[nt][3]));
        }
        mx0 = fmaxf(mx0, __shfl_xor_sync(~0u, mx0, 1));
        mx0 = fmaxf(mx0, __shfl_xor_sync(~0u, mx0, 2));
        mx1 = fmaxf(mx1, __shfl_xor_sync(~0u, mx1, 1));
        mx1 = fmaxf(mx1, __shfl_xor_sync(~0u, mx1, 2));

        float mn0 = fmaxf(m0, mx0), mn1 = fmaxf(m1, mx1);
        float c0 = __expf(m0 - mn0), c1 = __expf(m1 - mn1);
        l0 *= c0; l1 *= c1;
#pragma unroll
        for (int nt = 0; nt < 8; nt++) {
            o[nt][0] *= c0; o[nt][1] *= c0;
            o[nt][2] *= c1; o[nt][3] *= c1;
        }

        float s0 = 0.f, s1 = 0.f;
#pragma unroll
        for (int nt = 0; nt < 16; nt++) {
            float p0 = __expf(sacc[nt][0] - mn0);
            float p1 = __expf(sacc[nt][1] - mn0);
            float p2 = __expf(sacc[nt][2] - mn1);
            float p3 = __expf(sacc[nt][3] - mn1);
            s0 += p0 + p1; s1 += p2 + p3;
            int c = nt * 8 + 2 * tg;
            *(uint2*)&Ps[wm + g][c]     = make_uint2(f2tf32(p0), f2tf32(p1));
            *(uint2*)&Ps[wm + 8 + g][c] = make_uint2(f2tf32(p2), f2tf32(p3));
        }
        s0 += __shfl_xor_sync(~0u, s0, 1);
        s0 += __shfl_xor_sync(~0u, s0, 2);
        s1 += __shfl_xor_sync(~0u, s1, 1);
        s1 += __shfl_xor_sync(~0u, s1, 2);
        l0 += s0; l1 += s1;
        m0 = mn0; m1 = mn1;
        __syncthreads();   // (A) all S-mma done, Ps ready

        // issue next-V loads (hidden under PV-mma)
        float4 pv[8];
        if (more) {
#pragma unroll
            for (int i = 0; i < 8; i++) {
                int r = i * 16 + lr;
                pv[i] = *(const float4*)(base
                        + (size_t)((kt + 1) * 128 + r) * 3 * DIM_
                        + 2 * DIM_ + h * HD_ + ldq);
            }
        }

        // ---- O += P @ V ----
#pragma unroll
        for (int kk = 0; kk < 16; kk++) {
            uint32_t af[4];
            af[0] = Ps[wm + g][kk * 8 + tg];
            af[1] = Ps[wm + 8 + g][kk * 8 + tg];
            af[2] = Ps[wm + g][kk * 8 + tg + 4];
            af[3] = Ps[wm + 8 + g][kk * 8 + tg + 4];
#pragma unroll
            for (int nt = 0; nt < 8; nt++) {
                uint32_t b0 = Vs[nt * 8 + g][kk * 8 + tg];
                uint32_t b1 = Vs[nt * 8 + g][kk * 8 + tg + 4];
                mma_tf32(o[nt], af, b0, b1);
            }
        }

        if (more) {
#pragma unroll
            for (int i = 0; i < 8; i++) {
                int r = i * 16 + lr;
                *(uint4*)&Ks[r][ldq] =
                    make_uint4(f2tf32(pk[i].x), f2tf32(pk[i].y),
                               f2tf32(pk[i].z), f2tf32(pk[i].w));
            }
        }
        __syncthreads();   // (B) all PV-mma done -> Vs writable
        if (more) {
#pragma unroll
            for (int i = 0; i < 8; i++) {
                int r = i * 16 + lr;
                Vs[ldq + 0][r] = f2tf32(pv[i].x);
                Vs[ldq + 1][r] = f2tf32(pv[i].y);
                Vs[ldq + 2][r] = f2tf32(pv[i].z);
                Vs[ldq + 3][r] = f2tf32(pv[i].w);
            }
        }
    }

    // ---- Epilogue: normalize, round to tf32 (proj GEMM input), store ----
    const float inv0 = 1.f / l0, inv1 = 1.f / l1;
    float* out0 = attn_out + (size_t)(b * N_ + mt * 128 + wm + g) * DIM_ + h * HD_;
    float* out1 = out0 + (size_t)8 * DIM_;
#pragma unroll
    for (int nt = 0; nt < 8; nt++) {
        int c = nt * 8 + 2 * tg;
        *(float2*)(out0 + c) = make_float2(f2tf32f(o[nt][0] * inv0),
                                           f2tf32f(o[nt][1] * inv0));
        *(float2*)(out1 + c) = make_float2(f2tf32f(o[nt][2] * inv1),
                                           f2tf32f(o[nt][3] * inv1));
    }
}

// ---------------------------------------------------------------------------
extern "C" void kernel_launch(void* const* d_in, const int* in_sizes, int n_in,
                              void* d_out, int out_size)
{
    const float* x      = (const float*)d_in[0];   // [2,2048,1024]
    const float* w_qkv  = (const float*)d_in[1];   // [3072,1024]
    const float* w_proj = (const float*)d_in[2];   // [1024,1024]
    const float* b_proj = (const float*)d_in[3];   // [1024]
    float* out = (float*)d_out;                    // [2,2048,1024]

    float *qkv, *attn, *xr, *wq, *wp;
    cudaGetSymbolAddress((void**)&qkv,  g_qkv);
    cudaGetSymbolAddress((void**)&attn, g_attn);
    cudaGetSymbolAddress((void**)&xr,   g_x);
    cudaGetSymbolAddress((void**)&wq,   g_wqkv);
    cudaGetSymbolAddress((void**)&wp,   g_wproj);

    // Idempotent host-side config (capture-safe).
    cudaFuncSetAttribute(flash_attn,
                         cudaFuncAttributeMaxDynamicSharedMemorySize, FLASH_SMEM);
    cudaFuncSetAttribute(gemm_cp,
                         cudaFuncAttributeMaxDynamicSharedMemorySize, GEMM_SMEM);

    // 0) pre-round inputs to tf32 values
    round_tf32<<<(M_ * DIM_ / 4 + 255) / 256, 256>>>(x, xr, M_ * DIM_ / 4);
    round_tf32<<<(3 * DIM_ * DIM_ / 4 + 255) / 256, 256>>>(w_qkv, wq, 3 * DIM_ * DIM_ / 4);
    round_tf32<<<(DIM_ * DIM_ / 4 + 255) / 256, 256>>>(w_proj, wp, DIM_ * DIM_ / 4);

    // 1) qkv = x @ w_qkv^T   [4096,3072]  (outputs rounded for flash)
    gemm_cp<<<dim3(3 * DIM_ / 128, M_ / 128), 256, GEMM_SMEM>>>(
        xr, wq, nullptr, qkv, DIM_, DIM_, DIM_, 3 * DIM_, 1);

    // 2) fused attention -> [B,N,H,Dh] = [4096,1024] (outputs rounded)
    flash_attn<<<dim3(N_ / 128, H_, B_), 256, FLASH_SMEM>>>(qkv, attn);

    // 3) out = attn @ w_proj^T + b_proj
    gemm_cp<<<dim3(DIM_ / 128, M_ / 128), 256, GEMM_SMEM>>>(
        attn, wp, b_proj, out, DIM_, DIM_, DIM_, DIM_, 0);
}

// round 15
// speedup vs baseline: 1.6322x; 1.0083x over previous
#include <cuda_runtime.h>
#include <cuda_bf16.h>
#include <cstdint>

// Problem constants
#define B_    2
#define N_    2048
#define DIM_  1024
#define H_    16
#define HD_   64
#define M_    (B_ * N_)          // 4096
#define SCALE_ 0.125f

// Scratch (__device__ globals — allocation guards forbid cudaMalloc)
__device__ float g_qkv[(size_t)M_ * 3 * DIM_];           // [4096, 3072]
__device__ float g_attn[(size_t)M_ * DIM_];              // [4096, 1024]
__device__ float g_x[(size_t)M_ * DIM_];                 // rounded x
__device__ float g_wqkv[(size_t)3 * DIM_ * DIM_];        // rounded w_qkv
__device__ float g_wproj[(size_t)DIM_ * DIM_];           // rounded w_proj

// ---------------------------------------------------------------------------
// tf32 helpers
// ---------------------------------------------------------------------------
__device__ __forceinline__ uint32_t f2tf32(float x) {
    uint32_t r;
    asm("cvt.rna.tf32.f32 %0, %1;" : "=r"(r) : "f"(x));
    return r;
}
__device__ __forceinline__ float f2tf32f(float x) {
    return __uint_as_float(f2tf32(x));
}

__device__ __forceinline__ void mma_tf32(float c[4], const uint32_t a[4],
                                         const uint32_t b0, const uint32_t b1) {
    asm volatile(
        "mma.sync.aligned.m16n8k8.row.col.f32.tf32.tf32.f32 "
        "{%0,%1,%2,%3}, {%4,%5,%6,%7}, {%8,%9}, {%0,%1,%2,%3};"
        : "+f"(c[0]), "+f"(c[1]), "+f"(c[2]), "+f"(c[3])
        : "r"(a[0]), "r"(a[1]), "r"(a[2]), "r"(a[3]), "r"(b0), "r"(b1));
}

__device__ __forceinline__ void cpasync16(uint32_t s, const void* g) {
    asm volatile("cp.async.cg.shared.global [%0], [%1], 16;" :: "r"(s), "l"(g));
}

// ---------------------------------------------------------------------------
// Elementwise tf32 rounding (inputs pre-pass).
// ---------------------------------------------------------------------------
__global__ void __launch_bounds__(256)
round_tf32(const float* __restrict__ in, float* __restrict__ out, int n4)
{
    int i = blockIdx.x * 256 + threadIdx.x;
    if (i < n4) {
        float4 v = ((const float4*)in)[i];
        v.x = f2tf32f(v.x); v.y = f2tf32f(v.y);
        v.z = f2tf32f(v.z); v.w = f2tf32f(v.w);
        ((float4*)out)[i] = v;
    }
}

// ---------------------------------------------------------------------------
// 3-stage cp.async tf32 GEMM: C = A @ B^T (+ bias).
// Inputs MUST be pre-rounded to tf32 values (raw bits fed to mma).
// BM=BN=128, BK=32, 256 thr, 2 CTAs/SM (110.6 KB smem x2 = 221 KB < 228 KB).
// Per iter: wait(stage t) -> sync -> issue(stage t+2) -> mma(t). ONE barrier.
// ---------------------------------------------------------------------------
#define GSTRIDE 36
#define GSTAGE  (128 * GSTRIDE)               // words per matrix per stage
#define GEMM_SMEM (6 * GSTAGE * 4)            // 3 stages x (A+B) = 110592 B

__global__ void __launch_bounds__(256, 2)
gemm_cp(const float* __restrict__ A, const float* __restrict__ Bm,
        const float* __restrict__ bias, float* __restrict__ C,
        int Kd, int lda, int ldb, int ldc, int roundOut)
{
    extern __shared__ uint32_t gs[];
    // layout: As[3][128][36] then Bs[3][128][36]
    uint32_t (*As)[128][GSTRIDE] = (uint32_t(*)[128][GSTRIDE])gs;
    uint32_t (*Bs)[128][GSTRIDE] = (uint32_t(*)[128][GSTRIDE])(gs + 3 * GSTAGE);
    const uint32_t smemBase = (uint32_t)__cvta_generic_to_shared(gs);

    const int tid  = threadIdx.x;
    const int warp = tid >> 5, lane = tid & 31;
    const int g    = lane >> 2, tg = lane & 3;
    const int wm   = (warp & 1) * 64;
    const int wn   = (warp >> 1) * 32;
    const int rowBase = blockIdx.y * 128;
    const int colBase = blockIdx.x * 128;

    const int lr  = tid >> 3;            // 0..31
    const int lkq = (tid & 7) * 4;       // 0,4,...,28

    float acc[4][4][4];
#pragma unroll
    for (int i = 0; i < 4; i++)
#pragma unroll
        for (int j = 0; j < 4; j++)
#pragma unroll
            for (int e = 0; e < 4; e++) acc[i][j][e] = 0.f;

    const int nTiles = Kd / 32;

    auto load_stage = [&](int t, int s) {
        int k0 = t * 32;
#pragma unroll
        for (int i = 0; i < 4; i++) {
            int r = i * 32 + lr;
            cpasync16(smemBase + (uint32_t)(((s * 128 + r) * GSTRIDE + lkq) * 4),
                      A + (size_t)(rowBase + r) * lda + k0 + lkq);
            cpasync16(smemBase + (uint32_t)(((3 * GSTAGE + (s * 128 + r) * GSTRIDE) + lkq) * 4),
                      Bm + (size_t)(colBase + r) * ldb + k0 + lkq);
        }
        asm volatile("cp.async.commit_group;");
    };

    // prologue: stages 0 and 1 in flight
    load_stage(0, 0);
    load_stage(1, 1);

    for (int t = 0; t < nTiles; t++) {
        // ensure stage t resident (allow newest group in flight)
        if (t + 1 < nTiles)
            asm volatile("cp.async.wait_group 1;");
        else
            asm volatile("cp.async.wait_group 0;");
        __syncthreads();   // stage t visible; all reads of stage t-1 finished

        if (t + 2 < nTiles)
            load_stage(t + 2, (t + 2) % 3);

        const int buf = t % 3;
#pragma unroll
        for (int kb = 0; kb < 4; kb++) {
            const int kk = kb * 8;
            uint32_t af[4][4];
#pragma unroll
            for (int mt = 0; mt < 4; mt++) {
                int r0 = wm + mt * 16 + g;
                af[mt][0] = As[buf][r0][kk + tg];
                af[mt][1] = As[buf][r0 + 8][kk + tg];
                af[mt][2] = As[buf][r0][kk + tg + 4];
                af[mt][3] = As[buf][r0 + 8][kk + tg + 4];
            }
#pragma unroll
            for (int nt = 0; nt < 4; nt++) {
                int n0 = wn + nt * 8 + g;
                uint32_t b0 = Bs[buf][n0][kk + tg];
                uint32_t b1 = Bs[buf][n0][kk + tg + 4];
#pragma unroll
                for (int mt = 0; mt < 4; mt++)
                    mma_tf32(acc[mt][nt], af[mt], b0, b1);
            }
        }
    }

    // ---- epilogue ----
#pragma unroll
    for (int mt = 0; mt < 4; mt++) {
#pragma unroll
        for (int nt = 0; nt < 4; nt++) {
            int r = rowBase + wm + mt * 16 + g;
            int c = colBase + wn + nt * 8 + 2 * tg;
            float2 v0 = make_float2(acc[mt][nt][0], acc[mt][nt][1]);
            float2 v1 = make_float2(acc[mt][nt][2], acc[mt][nt][3]);
            if (bias) {
                float2 bb = *(const float2*)(bias + c);
                v0.x += bb.x; v0.y += bb.y;
                v1.x += bb.x; v1.y += bb.y;
            }
            if (roundOut) {
                v0.x = f2tf32f(v0.x); v0.y = f2tf32f(v0.y);
                v1.x = f2tf32f(v1.x); v1.y = f2tf32f(v1.y);
            }
            *(float2*)(C + (size_t)r * ldc + c)       = v0;
            *(float2*)(C + (size_t)(r + 8) * ldc + c) = v1;
        }
    }
}

// ---------------------------------------------------------------------------
// Fused flash attention, tf32. K tiles via cp.async (qkv pre-rounded -> raw
// bits are valid tf32 operands, no cvt, no transpose needed). V keeps the
// register-prefetch path (transposed store), raw bits. Q scaled by 2^-3
// (exponent-only -> stays tf32-valued).
// Grid (N/128, H, B), 256 thr = 8 warps; warp w owns q rows [w*16, w*16+16).
// ---------------------------------------------------------------------------
#define KSTRIDE 68
#define VSTRIDE 132
#define PSTRIDE 132
#define FLASH_SMEM ((128 * KSTRIDE + 64 * VSTRIDE + 128 * PSTRIDE) * 4)

__global__ void __launch_bounds__(256, 1)
flash_attn(const float* __restrict__ qkv, float* __restrict__ attn_out)
{
    extern __shared__ uint32_t sm[];
    uint32_t (*Ks)[KSTRIDE] = (uint32_t(*)[KSTRIDE])sm;
    uint32_t (*Vs)[VSTRIDE] = (uint32_t(*)[VSTRIDE])(sm + 128 * KSTRIDE);
    uint32_t (*Ps)[PSTRIDE] =
        (uint32_t(*)[PSTRIDE])(sm + 128 * KSTRIDE + 64 * VSTRIDE);
    const uint32_t ksBase = (uint32_t)__cvta_generic_to_shared(sm);

    const int tid  = threadIdx.x;
    const int warp = tid >> 5, lane = tid & 31;
    const int g    = lane >> 2, tg = lane & 3;
    const int wm   = warp * 16;
    const int mt   = blockIdx.x;
    const int h    = blockIdx.y;
    const int b    = blockIdx.z;

    const float* base = qkv + (size_t)b * N_ * 3 * DIM_;

    const int lr  = tid >> 4;            // 0..15
    const int ldq = (tid & 15) * 4;      // 0,4,...,60

    // ---- Prologue: issue K0 cp.async + V0 LDGs, stage Q, then assemble ----
#pragma unroll
    for (int i = 0; i < 8; i++) {
        int r = i * 16 + lr;
        cpasync16(ksBase + (uint32_t)((r * KSTRIDE + ldq) * 4),
                  base + (size_t)r * 3 * DIM_ + DIM_ + h * HD_ + ldq);
    }
    asm volatile("cp.async.commit_group;");

    float4 pv[8];
#pragma unroll
    for (int i = 0; i < 8; i++) {
        int r = i * 16 + lr;
        pv[i] = *(const float4*)(base + (size_t)r * 3 * DIM_
                                 + 2 * DIM_ + h * HD_ + ldq);
    }

#pragma unroll
    for (int i = 0; i < 8; i++) {
        int r = i * 16 + lr;
        float4 v = *(const float4*)(base + (size_t)(mt * 128 + r) * 3 * DIM_
                                    + h * HD_ + ldq);
        Ps[r][ldq + 0] = __float_as_uint(v.x * SCALE_);
        Ps[r][ldq + 1] = __float_as_uint(v.y * SCALE_);
        Ps[r][ldq + 2] = __float_as_uint(v.z * SCALE_);
        Ps[r][ldq + 3] = __float_as_uint(v.w * SCALE_);
    }
    __syncthreads();

    uint32_t qf[8][4];
#pragma unroll
    for (int kk = 0; kk < 8; kk++) {
        qf[kk][0] = Ps[wm + g][kk * 8 + tg];
        qf[kk][1] = Ps[wm + 8 + g][kk * 8 + tg];
        qf[kk][2] = Ps[wm + g][kk * 8 + tg + 4];
        qf[kk][3] = Ps[wm + 8 + g][kk * 8 + tg + 4];
    }

    // store V0 transposed (raw bits)
#pragma unroll
    for (int i = 0; i < 8; i++) {
        int r = i * 16 + lr;
        Vs[ldq + 0][r] = __float_as_uint(pv[i].x);
        Vs[ldq + 1][r] = __float_as_uint(pv[i].y);
        Vs[ldq + 2][r] = __float_as_uint(pv[i].z);
        Vs[ldq + 3][r] = __float_as_uint(pv[i].w);
    }
    asm volatile("cp.async.wait_group 0;");
    __syncthreads();   // Ps free, K0 + V0 visible to all

    float o[8][4];
#pragma unroll
    for (int nt = 0; nt < 8; nt++)
#pragma unroll
        for (int e = 0; e < 4; e++) o[nt][e] = 0.f;
    float m0 = -1e30f, m1 = -1e30f, l0 = 0.f, l1 = 0.f;

    constexpr int NT = N_ / 128;
    for (int kt = 0; kt < NT; kt++) {
        const bool more = (kt + 1 < NT);

        // ---- S = Q @ K^T : warp strip [16 x 128] ----
        float sacc[16][4];
#pragma unroll
        for (int nt = 0; nt < 16; nt++)
#pragma unroll
            for (int e = 0; e < 4; e++) sacc[nt][e] = 0.f;
#pragma unroll
        for (int kk = 0; kk < 8; kk++) {
#pragma unroll
            for (int nt = 0; nt < 16; nt++) {
                uint32_t b0 = Ks[nt * 8 + g][kk * 8 + tg];
                uint32_t b1 = Ks[nt * 8 + g][kk * 8 + tg + 4];
                mma_tf32(sacc[nt], qf[kk], b0, b1);
            }
        }

        // ---- online softmax (rows wm+g, wm+8+g) ----
        float mx0 = -1e30f, mx1 = -1e30f;
#pragma unroll
        for (int nt = 0; nt < 16; nt++) {
            mx0 = fmaxf(mx0, fmaxf(sacc[nt][0], sacc[nt][1]));
            mx1 = fmaxf(mx1, fmaxf(sacc[nt][2], sacc[nt][3]));
        }
        mx0 = fmaxf(mx0, __shfl_xor_sync(~0u, mx0, 1));
        mx0 = fmaxf(mx0, __shfl_xor_sync(~0u, mx0, 2));
        mx1 = fmaxf(mx1, __shfl_xor_sync(~0u, mx1, 1));
        mx1 = fmaxf(mx1, __shfl_xor_sync(~0u, mx1, 2));

        float mn0 = fmaxf(m0, mx0), mn1 = fmaxf(m1, mx1);
        float c0 = __expf(m0 - mn0), c1 = __expf(m1 - mn1);
        l0 *= c0; l1 *= c1;
#pragma unroll
        for (int nt = 0; nt < 8; nt++) {
            o[nt][0] *= c0; o[nt][1] *= c0;
            o[nt][2] *= c1; o[nt][3] *= c1;
        }

        float s0 = 0.f, s1 = 0.f;
#pragma unroll
        for (int nt = 0; nt < 16; nt++) {
            float p0 = __expf(sacc[nt][0] - mn0);
            float p1 = __expf(sacc[nt][1] - mn0);
            float p2 = __expf(sacc[nt][2] - mn1);
            float p3 = __expf(sacc[nt][3] - mn1);
            s0 += p0 + p1; s1 += p2 + p3;
            int c = nt * 8 + 2 * tg;
            *(uint2*)&Ps[wm + g][c]     = make_uint2(f2tf32(p0), f2tf32(p1));
            *(uint2*)&Ps[wm + 8 + g][c] = make_uint2(f2tf32(p2), f2tf32(p3));
        }
        s0 += __shfl_xor_sync(~0u, s0, 1);
        s0 += __shfl_xor_sync(~0u, s0, 2);
        s1 += __shfl_xor_sync(~0u, s1, 1);
        s1 += __shfl_xor_sync(~0u, s1, 2);
        l0 += s0; l1 += s1;
        m0 = mn0; m1 = mn1;
        __syncthreads();   // (A) all S-mma done (Ks free), Ps ready

        // issue next-K cp.async + next-V LDGs (hidden under PV-mma)
        if (more) {
#pragma unroll
            for (int i = 0; i < 8; i++) {
                int r = i * 16 + lr;
                cpasync16(ksBase + (uint32_t)((r * KSTRIDE + ldq) * 4),
                          base + (size_t)((kt + 1) * 128 + r) * 3 * DIM_
                          + DIM_ + h * HD_ + ldq);
            }
            asm volatile("cp.async.commit_group;");
#pragma unroll
            for (int i = 0; i < 8; i++) {
                int r = i * 16 + lr;
                pv[i] = *(const float4*)(base
                        + (size_t)((kt + 1) * 128 + r) * 3 * DIM_
                        + 2 * DIM_ + h * HD_ + ldq);
            }
        }

        // ---- O += P @ V ----
#pragma unroll
        for (int kk = 0; kk < 16; kk++) {
            uint32_t af[4];
            af[0] = Ps[wm + g][kk * 8 + tg];
            af[1] = Ps[wm + 8 + g][kk * 8 + tg];
            af[2] = Ps[wm + g][kk * 8 + tg + 4];
            af[3] = Ps[wm + 8 + g][kk * 8 + tg + 4];
#pragma unroll
            for (int nt = 0; nt < 8; nt++) {
                uint32_t b0 = Vs[nt * 8 + g][kk * 8 + tg];
                uint32_t b1 = Vs[nt * 8 + g][kk * 8 + tg + 4];
                mma_tf32(o[nt], af, b0, b1);
            }
        }

        asm volatile("cp.async.wait_group 0;");
        __syncthreads();   // (B) PV done (Vs free); next K visible to all
        if (more) {
#pragma unroll
            for (int i = 0; i < 8; i++) {
                int r = i * 16 + lr;
                Vs[ldq + 0][r] = __float_as_uint(pv[i].x);
                Vs[ldq + 1][r] = __float_as_uint(pv[i].y);
                Vs[ldq + 2][r] = __float_as_uint(pv[i].z);
                Vs[ldq + 3][r] = __float_as_uint(pv[i].w);
            }
        }
    }

    // ---- Epilogue: normalize, round to tf32 (proj GEMM input), store ----
    const float inv0 = 1.f / l0, inv1 = 1.f / l1;
    float* out0 = attn_out + (size_t)(b * N_ + mt * 128 + wm + g) * DIM_ + h * HD_;
    float* out1 = out0 + (size_t)8 * DIM_;
#pragma unroll
    for (int nt = 0; nt < 8; nt++) {
        int c = nt * 8 + 2 * tg;
        *(float2*)(out0 + c) = make_float2(f2tf32f(o[nt][0] * inv0),
                                           f2tf32f(o[nt][1] * inv0));
        *(float2*)(out1 + c) = make_float2(f2tf32f(o[nt][2] * inv1),
                                           f2tf32f(o[nt][3] * inv1));
    }
}

// ---------------------------------------------------------------------------
extern "C" void kernel_launch(void* const* d_in, const int* in_sizes, int n_in,
                              void* d_out, int out_size)
{
    const float* x      = (const float*)d_in[0];   // [2,2048,1024]
    const float* w_qkv  = (const float*)d_in[1];   // [3072,1024]
    const float* w_proj = (const float*)d_in[2];   // [1024,1024]
    const float* b_proj = (const float*)d_in[3];   // [1024]
    float* out = (float*)d_out;                    // [2,2048,1024]

    float *qkv, *attn, *xr, *wq, *wp;
    cudaGetSymbolAddress((void**)&qkv,  g_qkv);
    cudaGetSymbolAddress((void**)&attn, g_attn);
    cudaGetSymbolAddress((void**)&xr,   g_x);
    cudaGetSymbolAddress((void**)&wq,   g_wqkv);
    cudaGetSymbolAddress((void**)&wp,   g_wproj);

    // Idempotent host-side config (capture-safe).
    cudaFuncSetAttribute(flash_attn,
                         cudaFuncAttributeMaxDynamicSharedMemorySize, FLASH_SMEM);
    cudaFuncSetAttribute(gemm_cp,
                         cudaFuncAttributeMaxDynamicSharedMemorySize, GEMM_SMEM);

    // 0) pre-round inputs to tf32 values
    round_tf32<<<(M_ * DIM_ / 4 + 255) / 256, 256>>>(x, xr, M_ * DIM_ / 4);
    round_tf32<<<(3 * DIM_ * DIM_ / 4 + 255) / 256, 256>>>(w_qkv, wq, 3 * DIM_ * DIM_ / 4);
    round_tf32<<<(DIM_ * DIM_ / 4 + 255) / 256, 256>>>(w_proj, wp, DIM_ * DIM_ / 4);

    // 1) qkv = x @ w_qkv^T   [4096,3072]  (outputs rounded for flash)
    gemm_cp<<<dim3(3 * DIM_ / 128, M_ / 128), 256, GEMM_SMEM>>>(
        xr, wq, nullptr, qkv, DIM_, DIM_, DIM_, 3 * DIM_, 1);

    // 2) fused attention -> [B,N,H,Dh] = [4096,1024] (outputs rounded)
    flash_attn<<<dim3(N_ / 128, H_, B_), 256, FLASH_SMEM>>>(qkv, attn);

    // 3) out = attn @ w_proj^T + b_proj
    gemm_cp<<<dim3(DIM_ / 128, M_ / 128), 256, GEMM_SMEM>>>(
        attn, wp, b_proj, out, DIM_, DIM_, DIM_, DIM_, 0);
}